// round 6
// baseline (speedup 1.0000x reference)
#include <cuda_runtime.h>
#include <math.h>

// Problem constants (fixed shapes from reference setup_inputs)
#define BB 32
#define SS 64
#define HH 256
#define CELLS_PER_BATCH (SS * SS)   // 4096
#define EPSF 1e-8f

// Per-batch accumulators + precomputed 1/(||q||+eps). Device globals (no alloc allowed).
__device__ float g_pos_acc[BB];
__device__ float g_neg_acc[BB];
__device__ float g_invq[BB];

// ---------------------------------------------------------------------------
// Kernel 0: zero accumulators (required every graph replay) and compute invq[b].
// 1 block, 1024 threads: warp w handles batch w.
// ---------------------------------------------------------------------------
__global__ void __launch_bounds__(1024) cl_init_kernel(const float* __restrict__ pos_query) {
    const int wid  = threadIdx.x >> 5;
    const int lane = threadIdx.x & 31;
    if (wid < BB) {
        const float4* q = reinterpret_cast<const float4*>(pos_query + (size_t)wid * HH);
        float ss = 0.0f;
        #pragma unroll
        for (int i = 0; i < 2; i++) {
            float4 v = q[lane + i * 32];   // 64 float4 per batch row
            ss += v.x * v.x + v.y * v.y + v.z * v.z + v.w * v.w;
        }
        #pragma unroll
        for (int o = 16; o > 0; o >>= 1)
            ss += __shfl_xor_sync(0xFFFFFFFFu, ss, o);
        if (lane == 0) {
            g_invq[wid]    = 1.0f / (sqrtf(ss) + EPSF);
            g_pos_acc[wid] = 0.0f;
            g_neg_acc[wid] = 0.0f;
        }
    }
}

// ---------------------------------------------------------------------------
// Kernel 1: main reduction. One warp per cell iteration, 16 cells per warp.
// Grid: BB * 32 blocks (32 blocks per batch), 256 threads (8 warps) per block.
// Cells with neither mask set are skipped (only int mask reads) -> ~65% of
// tmap HBM traffic is never issued. Masks are int32 (bool inputs are
// materialized as int32 per the harness dtype contract).
// ---------------------------------------------------------------------------
__global__ void __launch_bounds__(256) cl_main_kernel(
    const float* __restrict__ tmap,
    const float* __restrict__ pos_query,
    const int*   __restrict__ mpos,
    const int*   __restrict__ mneg)
{
    const int b        = blockIdx.x >> 5;        // 32 blocks per batch
    const int blk_in_b = blockIdx.x & 31;
    const int wid      = threadIdx.x >> 5;
    const int lane     = threadIdx.x & 31;

    // This warp's 16 consecutive cells within batch b
    const int cell0 = b * CELLS_PER_BATCH + blk_in_b * 128 + wid * 16;

    // Query chunk for this lane (same for all 16 cells; stays in registers)
    const float4* qp = reinterpret_cast<const float4*>(pos_query + (size_t)b * HH);
    const float4 q0 = qp[lane];
    const float4 q1 = qp[lane + 32];
    const float invq = g_invq[b];

    float psum = 0.0f, nsum = 0.0f;

    #pragma unroll 4
    for (int k = 0; k < 16; k++) {
        const int c = cell0 + k;
        const int pm = mpos[c];
        const int nm = mneg[c];
        if ((pm | nm) == 0) continue;            // skip dead cell: no tmap read

        const float4* tp = reinterpret_cast<const float4*>(tmap + (size_t)c * HH);
        const float4 t0 = tp[lane];
        const float4 t1 = tp[lane + 32];

        float dq = t0.x * q0.x + t0.y * q0.y + t0.z * q0.z + t0.w * q0.w
                 + t1.x * q1.x + t1.y * q1.y + t1.z * q1.z + t1.w * q1.w;
        float dt = t0.x * t0.x + t0.y * t0.y + t0.z * t0.z + t0.w * t0.w
                 + t1.x * t1.x + t1.y * t1.y + t1.z * t1.z + t1.w * t1.w;

        #pragma unroll
        for (int o = 16; o > 0; o >>= 1) {
            dq += __shfl_xor_sync(0xFFFFFFFFu, dq, o);
            dt += __shfl_xor_sync(0xFFFFFFFFu, dt, o);
        }

        // s = dot(t,q) / ||t|| / (||q||+eps); the reference's inner
        // renormalize (||u||+eps, ||u||~=1) perturbs s by ~1e-7 << tolerance.
        const float s = dq * rsqrtf(dt) * invq;
        const float e = expf(s);                 // TAO = 1.0
        if (pm) psum += e;
        if (nm) nsum += e;
    }

    // Block reduction: lane 0 of each warp -> smem -> 2 atomics per block.
    __shared__ float s_p[8];
    __shared__ float s_n[8];
    if (lane == 0) { s_p[wid] = psum; s_n[wid] = nsum; }
    __syncthreads();
    if (threadIdx.x == 0) {
        float ap = 0.0f, an = 0.0f;
        #pragma unroll
        for (int i = 0; i < 8; i++) { ap += s_p[i]; an += s_n[i]; }
        if (ap != 0.0f) atomicAdd(&g_pos_acc[b], ap);
        if (an != 0.0f) atomicAdd(&g_neg_acc[b], an);
    }
}

// ---------------------------------------------------------------------------
// Kernel 2: final loss. 1 warp; lane b handles batch b.
// valid(b) = (pos set nonempty) & (neg set nonempty)  <=>  both sums > 0
// (exp(.) is strictly positive).
// ---------------------------------------------------------------------------
__global__ void cl_final_kernel(float* __restrict__ out) {
    const int lane = threadIdx.x;
    float li = 0.0f;
    int   v  = 0;
    if (lane < BB) {
        const float num = g_pos_acc[lane];
        const float ng  = g_neg_acc[lane];
        if (num > 0.0f && ng > 0.0f) {
            v = 1;
            li = -logf(num / (num + ng + EPSF));
        }
    }
    #pragma unroll
    for (int o = 16; o > 0; o >>= 1) {
        li += __shfl_xor_sync(0xFFFFFFFFu, li, o);
        v  += __shfl_xor_sync(0xFFFFFFFFu, v, o);
    }
    if (lane == 0) {
        out[0] = li / (float)(v > 0 ? v : 1);
    }
}

// ---------------------------------------------------------------------------
// Launch. Input order (metadata / setup_inputs dict order):
//   d_in[0] = pos_query  (B,H)     float32
//   d_in[1] = tmap       (B,S,S,H) float32
//   d_in[2] = mask2d_pos (B,S,S)   bool -> int32
//   d_in[3] = mask2d_neg (B,S,S)   bool -> int32
// Output: scalar float32.
// ---------------------------------------------------------------------------
extern "C" void kernel_launch(void* const* d_in, const int* in_sizes, int n_in,
                              void* d_out, int out_size) {
    (void)in_sizes; (void)n_in; (void)out_size;
    const float* pos_query = (const float*)d_in[0];
    const float* tmap      = (const float*)d_in[1];
    const int*   mpos      = (const int*)d_in[2];
    const int*   mneg      = (const int*)d_in[3];
    float*       out       = (float*)d_out;

    cl_init_kernel<<<1, 1024>>>(pos_query);
    cl_main_kernel<<<BB * 32, 256>>>(tmap, pos_query, mpos, mneg);
    cl_final_kernel<<<1, 32>>>(out);
}

// round 7
// speedup vs baseline: 1.0259x; 1.0259x over previous
#include <cuda_runtime.h>
#include <math.h>

// Problem constants (fixed shapes from reference setup_inputs)
#define BB 32
#define SS 64
#define HH 256
#define CELLS_PER_BATCH (SS * SS)   // 4096
#define EPSF 1e-8f

// Per-batch accumulators + precomputed 1/(||q||+eps). Device globals (no alloc allowed).
__device__ float g_pos_acc[BB];
__device__ float g_neg_acc[BB];
__device__ float g_invq[BB];

// ---------------------------------------------------------------------------
// Kernel 0: zero accumulators (required every graph replay) and compute invq[b].
// 1 block, 1024 threads: warp w handles batch w.
// ---------------------------------------------------------------------------
__global__ void __launch_bounds__(1024) cl_init_kernel(const float* __restrict__ pos_query) {
    const int wid  = threadIdx.x >> 5;
    const int lane = threadIdx.x & 31;
    if (wid < BB) {
        const float4* q = reinterpret_cast<const float4*>(pos_query + (size_t)wid * HH);
        float ss = 0.0f;
        #pragma unroll
        for (int i = 0; i < 2; i++) {
            float4 v = q[lane + i * 32];   // 64 float4 per batch row
            ss += v.x * v.x + v.y * v.y + v.z * v.z + v.w * v.w;
        }
        #pragma unroll
        for (int o = 16; o > 0; o >>= 1)
            ss += __shfl_xor_sync(0xFFFFFFFFu, ss, o);
        if (lane == 0) {
            g_invq[wid]    = 1.0f / (sqrtf(ss) + EPSF);
            g_pos_acc[wid] = 0.0f;
            g_neg_acc[wid] = 0.0f;
        }
    }
}

// ---------------------------------------------------------------------------
// Kernel 1: main reduction. One warp per cell iteration, 16 cells per warp.
// Grid: BB * 32 blocks (32 blocks per batch), 256 threads (8 warps) per block.
// Cells with neither mask set are skipped (only int mask reads) -> ~65% of
// tmap HBM traffic is never issued. Masks are int32 (bool inputs are
// materialized as int32 per the harness dtype contract).
// ---------------------------------------------------------------------------
__global__ void __launch_bounds__(256) cl_main_kernel(
    const float* __restrict__ tmap,
    const float* __restrict__ pos_query,
    const int*   __restrict__ mpos,
    const int*   __restrict__ mneg)
{
    const int b        = blockIdx.x >> 5;        // 32 blocks per batch
    const int blk_in_b = blockIdx.x & 31;
    const int wid      = threadIdx.x >> 5;
    const int lane     = threadIdx.x & 31;

    // This warp's 16 consecutive cells within batch b
    const int cell0 = b * CELLS_PER_BATCH + blk_in_b * 128 + wid * 16;

    // Query chunk for this lane (same for all 16 cells; stays in registers)
    const float4* qp = reinterpret_cast<const float4*>(pos_query + (size_t)b * HH);
    const float4 q0 = qp[lane];
    const float4 q1 = qp[lane + 32];
    const float invq = g_invq[b];

    float psum = 0.0f, nsum = 0.0f;

    #pragma unroll 4
    for (int k = 0; k < 16; k++) {
        const int c = cell0 + k;
        const int pm = mpos[c];
        const int nm = mneg[c];
        if ((pm | nm) == 0) continue;            // skip dead cell: no tmap read

        const float4* tp = reinterpret_cast<const float4*>(tmap + (size_t)c * HH);
        const float4 t0 = tp[lane];
        const float4 t1 = tp[lane + 32];

        float dq = t0.x * q0.x + t0.y * q0.y + t0.z * q0.z + t0.w * q0.w
                 + t1.x * q1.x + t1.y * q1.y + t1.z * q1.z + t1.w * q1.w;
        float dt = t0.x * t0.x + t0.y * t0.y + t0.z * t0.z + t0.w * t0.w
                 + t1.x * t1.x + t1.y * t1.y + t1.z * t1.z + t1.w * t1.w;

        #pragma unroll
        for (int o = 16; o > 0; o >>= 1) {
            dq += __shfl_xor_sync(0xFFFFFFFFu, dq, o);
            dt += __shfl_xor_sync(0xFFFFFFFFu, dt, o);
        }

        // s = dot(t,q) / ||t|| / (||q||+eps); the reference's inner
        // renormalize (||u||+eps, ||u||~=1) perturbs s by ~1e-7 << tolerance.
        const float s = dq * rsqrtf(dt) * invq;
        const float e = expf(s);                 // TAO = 1.0
        if (pm) psum += e;
        if (nm) nsum += e;
    }

    // Block reduction: lane 0 of each warp -> smem -> 2 atomics per block.
    __shared__ float s_p[8];
    __shared__ float s_n[8];
    if (lane == 0) { s_p[wid] = psum; s_n[wid] = nsum; }
    __syncthreads();
    if (threadIdx.x == 0) {
        float ap = 0.0f, an = 0.0f;
        #pragma unroll
        for (int i = 0; i < 8; i++) { ap += s_p[i]; an += s_n[i]; }
        if (ap != 0.0f) atomicAdd(&g_pos_acc[b], ap);
        if (an != 0.0f) atomicAdd(&g_neg_acc[b], an);
    }
}

// ---------------------------------------------------------------------------
// Kernel 2: final loss. 1 warp; lane b handles batch b.
// valid(b) = (pos set nonempty) & (neg set nonempty)  <=>  both sums > 0
// (exp(.) is strictly positive).
// ---------------------------------------------------------------------------
__global__ void cl_final_kernel(float* __restrict__ out) {
    const int lane = threadIdx.x;
    float li = 0.0f;
    int   v  = 0;
    if (lane < BB) {
        const float num = g_pos_acc[lane];
        const float ng  = g_neg_acc[lane];
        if (num > 0.0f && ng > 0.0f) {
            v = 1;
            li = -logf(num / (num + ng + EPSF));
        }
    }
    #pragma unroll
    for (int o = 16; o > 0; o >>= 1) {
        li += __shfl_xor_sync(0xFFFFFFFFu, li, o);
        v  += __shfl_xor_sync(0xFFFFFFFFu, v, o);
    }
    if (lane == 0) {
        out[0] = li / (float)(v > 0 ? v : 1);
    }
}

// ---------------------------------------------------------------------------
// Launch. Input order (metadata / setup_inputs dict order):
//   d_in[0] = pos_query  (B,H)     float32
//   d_in[1] = tmap       (B,S,S,H) float32
//   d_in[2] = mask2d_pos (B,S,S)   bool -> int32
//   d_in[3] = mask2d_neg (B,S,S)   bool -> int32
// Output: scalar float32.
// ---------------------------------------------------------------------------
extern "C" void kernel_launch(void* const* d_in, const int* in_sizes, int n_in,
                              void* d_out, int out_size) {
    (void)in_sizes; (void)n_in; (void)out_size;
    const float* pos_query = (const float*)d_in[0];
    const float* tmap      = (const float*)d_in[1];
    const int*   mpos      = (const int*)d_in[2];
    const int*   mneg      = (const int*)d_in[3];
    float*       out       = (float*)d_out;

    cl_init_kernel<<<1, 1024>>>(pos_query);
    cl_main_kernel<<<BB * 32, 256>>>(tmap, pos_query, mpos, mneg);
    cl_final_kernel<<<1, 32>>>(out);
}